// round 12
// baseline (speedup 1.0000x reference)
#include <cuda_runtime.h>
#include <cuda_fp16.h>
#include <cstdint>

// Problem constants
#define BB 8
#define SS 64
#define NN 256
#define FF 16
#define HH 16
#define CC 4096            // N*H  (= GEMM M)
#define COLS 512           // B*S  (= GEMM Ncol)
#define KTOT 12288         // C*3  (= GEMM K, native interleaved k = c*3+tap)
#define ALPHA 0.2f
#define EPS 1e-5f

// GEMM tiling (fp16 HMMA, single-term: D = A*B)
#define BK 64                       // fp16 K per stage (128B rows)
#define TILEB 16384                 // 128 rows x 64 fp16 x 2B, xor-swizzled
#define STAGEB 32768                // A, B tiles
#define NSTAGE 4
#define NIT (KTOT / BK)             // 192
#define SMEM_DYN (NSTAGE * STAGEB)  // 131072 (also covers epilogue tile)
#define LDSD 132                    // epilogue smem stride (floats)

// ---------------- device scratch (no allocations allowed) -------------------
__device__ __half g_Bf[(size_t)COLS * KTOT];     // fp16 data (interleaved K)

// ---------------- PTX helpers ----------------------------------------------
__device__ __forceinline__ void cp16(unsigned dst, const void* src) {
    asm volatile("cp.async.cg.shared.global [%0], [%1], 16;" :: "r"(dst), "l"(src) : "memory");
}
__device__ __forceinline__ void cp_commit() {
    asm volatile("cp.async.commit_group;" ::: "memory");
}
__device__ __forceinline__ void ldsm4(unsigned* r, unsigned addr) {
    asm volatile("ldmatrix.sync.aligned.m8n8.x4.shared.b16 {%0,%1,%2,%3}, [%4];"
                 : "=r"(r[0]), "=r"(r[1]), "=r"(r[2]), "=r"(r[3]) : "r"(addr));
}
__device__ __forceinline__ void sts128(unsigned addr, unsigned v0, unsigned v1,
                                       unsigned v2, unsigned v3) {
    asm volatile("st.shared.v4.b32 [%0], {%1,%2,%3,%4};"
                 :: "r"(addr), "r"(v0), "r"(v1), "r"(v2), "r"(v3) : "memory");
}
__device__ __forceinline__ void mma16816h(float* d, const unsigned* a, const unsigned* b) {
    asm volatile(
        "mma.sync.aligned.m16n8k16.row.col.f32.f16.f16.f32 "
        "{%0,%1,%2,%3}, {%4,%5,%6,%7}, {%8,%9}, {%0,%1,%2,%3};"
        : "+f"(d[0]), "+f"(d[1]), "+f"(d[2]), "+f"(d[3])
        : "r"(a[0]), "r"(a[1]), "r"(a[2]), "r"(a[3]), "r"(b[0]), "r"(b[1]));
}
__device__ __forceinline__ unsigned packh2(float x, float y) {
    __half2 h = __floats2half2_rn(x, y);
    return *reinterpret_cast<unsigned*>(&h);
}

// ---------------------------------------------------------------------------
// GAT kernel: mask ballot + wh + masked softmax + spatial + B scatter.
// grid = 512 (b*s), block = 256.
// ---------------------------------------------------------------------------
__global__ __launch_bounds__(256) void k_gat(const float* __restrict__ x,
                                             const float* __restrict__ adj,
                                             const float* __restrict__ W,
                                             const float* __restrict__ a1v,
                                             const float* __restrict__ a2v) {
    __shared__ float    sW[FF * HH];
    __shared__ float    sa1[HH], sa2[HH];
    __shared__ float    sWh[NN * HH];
    __shared__ float    sf2[NN];
    __shared__ unsigned smask[NN * 8];

    int bs = blockIdx.x;
    int t = threadIdx.x;
    int wid = t >> 5, lane = t & 31;

    sW[t] = W[t];
    if (t < HH) { sa1[t] = a1v[t]; sa2[t] = a2v[t]; }

    // mask ballot: each warp covers idx = wid + 8k, unrolled x4 for MLP
#pragma unroll 1
    for (int idx = wid; idx < NN * 8; idx += 32) {
        float v0 = adj[(idx >> 3) * NN + (idx & 7) * 32 + lane];
        float v1 = adj[((idx + 8) >> 3) * NN + ((idx + 8) & 7) * 32 + lane];
        float v2 = adj[((idx + 16) >> 3) * NN + ((idx + 16) & 7) * 32 + lane];
        float v3 = adj[((idx + 24) >> 3) * NN + ((idx + 24) & 7) * 32 + lane];
        unsigned m0 = __ballot_sync(0xffffffffu, v0 > 0.0f);
        unsigned m1 = __ballot_sync(0xffffffffu, v1 > 0.0f);
        unsigned m2 = __ballot_sync(0xffffffffu, v2 > 0.0f);
        unsigned m3 = __ballot_sync(0xffffffffu, v3 > 0.0f);
        if (lane == 0) {
            smask[idx] = m0; smask[idx + 8] = m1;
            smask[idx + 16] = m2; smask[idx + 24] = m3;
        }
    }
    __syncthreads();

    // ---- Wh = x @ W ; f1, f2 ----
    const float* xr = x + (size_t)(bs * NN + t) * FF;
    float xv[FF];
#pragma unroll
    for (int f = 0; f < FF; f += 4) {
        float4 v = *(const float4*)(xr + f);
        xv[f] = v.x; xv[f + 1] = v.y; xv[f + 2] = v.z; xv[f + 3] = v.w;
    }
    float wh[HH];
#pragma unroll
    for (int h = 0; h < HH; h++) wh[h] = 0.0f;
#pragma unroll
    for (int f = 0; f < FF; f++)
#pragma unroll
        for (int h = 0; h < HH; h++) wh[h] += xv[f] * sW[f * HH + h];

    float f1i = 0.0f, f2i = 0.0f;
#pragma unroll
    for (int h = 0; h < HH; h++) { f1i += wh[h] * sa1[h]; f2i += wh[h] * sa2[h]; }

#pragma unroll
    for (int h = 0; h < HH; h++) sWh[t * HH + h] = wh[h];
    sf2[t] = f2i;
    __syncthreads();

    // ---- masked softmax: pass 1 max ----
    float m = -1e30f;
#pragma unroll 1
    for (int jw = 0; jw < 8; jw++) {
        unsigned wd = smask[t * 8 + jw];
#pragma unroll
        for (int bit = 0; bit < 32; bit++) {
            float e = f1i + sf2[jw * 32 + bit];
            e = e > 0.0f ? e : ALPHA * e;
            if ((wd >> bit) & 1u) m = fmaxf(m, e);
        }
    }

    // ---- pass 2: exp/sum + weighted accumulate ----
    float sum = 0.0f;
    float acc[HH];
#pragma unroll
    for (int h = 0; h < HH; h++) acc[h] = 0.0f;

#pragma unroll 1
    for (int jw = 0; jw < 8; jw++) {
        unsigned wd = smask[t * 8 + jw];
#pragma unroll
        for (int bit = 0; bit < 32; bit++) {
            int j = jw * 32 + bit;
            float e = f1i + sf2[j];
            e = e > 0.0f ? e : ALPHA * e;
            float w = ((wd >> bit) & 1u) ? __expf(e - m) : 0.0f;
            sum += w;
#pragma unroll
            for (int h = 0; h < HH; h++) acc[h] += w * sWh[j * HH + h];
        }
    }

    float inv = 1.0f / sum;
    __half hv[16];
#pragma unroll
    for (int h = 0; h < HH; h++) hv[h] = __float2half_rn(acc[h] * inv);

    // ---- scatter into interleaved B: k = c*3 + tap ----
    int s = bs & 63;
    int c0 = t * HH;
    const __half zh = __float2half(0.0f);
    __half* own = g_Bf + (size_t)bs * KTOT;
    __half* nxt = g_Bf + (size_t)(bs + 1) * KTOT;
    __half* prv = g_Bf + (size_t)(bs - 1) * KTOT;
    bool hasN = (s < 63), hasP = (s > 0);
#pragma unroll
    for (int h = 0; h < HH; h++) {
        int k3 = (c0 + h) * 3;
        own[k3 + 1] = hv[h];
        if (hasN) nxt[k3] = hv[h];
        if (hasP) prv[k3 + 2] = hv[h];
        if (!hasP) own[k3] = zh;          // s == 0: zero tap 0
        if (!hasN) own[k3 + 2] = zh;      // s == 63: zero tap 2
    }
}

// ---------------------------------------------------------------------------
// Conv GEMM + fused epilogue. A converted fp32->fp16 in-kernel.
// 128x128 CTA tile, BK=64, 4 stages, 8 warps (4M x 2N), warp tile m32n64.
// ---------------------------------------------------------------------------
__device__ __forceinline__ void issue_stage_B(unsigned sbs, int kb, int t,
                                              const __half* bG) {
    int row = t >> 1;
    int h2 = t & 1;
    unsigned rowB = (unsigned)(row * 128);
    unsigned swz = (unsigned)((row & 7) << 4);
    size_t go = (size_t)row * KTOT + kb;
#pragma unroll
    for (int j = 0; j < 4; j++) {
        int cidx = j * 2 + h2;
        unsigned dsw = rowB + (((unsigned)(cidx * 16)) ^ swz);
        cp16(sbs + 16384 + dsw, bG + go + cidx * 8);
    }
    cp_commit();
}

__device__ __forceinline__ void ldgA(float4* av, const float* aG, int kb, int t) {
    int row = t >> 1, h2 = t & 1;
    const float* src = aG + (size_t)row * KTOT + kb;
#pragma unroll
    for (int j = 0; j < 4; j++) {
        int cidx = j * 2 + h2;
        av[j * 2]     = *(const float4*)(src + cidx * 8);
        av[j * 2 + 1] = *(const float4*)(src + cidx * 8 + 4);
    }
}

__device__ __forceinline__ void stsA(unsigned sbs, const float4* av, int t) {
    int row = t >> 1, h2 = t & 1;
    unsigned rowB = (unsigned)(row * 128);
    unsigned swz = (unsigned)((row & 7) << 4);
#pragma unroll
    for (int j = 0; j < 4; j++) {
        int cidx = j * 2 + h2;
        float4 a = av[j * 2], b = av[j * 2 + 1];
        unsigned u0 = packh2(a.x, a.y);
        unsigned u1 = packh2(a.z, a.w);
        unsigned u2 = packh2(b.x, b.y);
        unsigned u3 = packh2(b.z, b.w);
        unsigned dsw = rowB + (((unsigned)(cidx * 16)) ^ swz);
        sts128(sbs + dsw, u0, u1, u2, u3);
    }
}

__global__ __launch_bounds__(256, 1) void k_conv_mma(
        const float* __restrict__ wsrc,
        const float* __restrict__ x,
        const float* __restrict__ conv_b,
        const float* __restrict__ bn_g, const float* __restrict__ bn_b,
        const float* __restrict__ bn_m, const float* __restrict__ bn_v,
        const float* __restrict__ ln_g, const float* __restrict__ ln_b,
        float* __restrict__ out) {
    extern __shared__ __align__(1024) char smem[];
    unsigned sb0 = (unsigned)__cvta_generic_to_shared(smem);

    int t = threadIdx.x;
    int wid = t >> 5;
    int L = t & 31;
    int wm = wid & 3;          // 4 warps along M (o)
    int wn = wid >> 2;         // 2 warps along N (col)
    int colBase = blockIdx.x * 128;
    int oBase = blockIdx.y * 128;

    const float* aG = wsrc + (size_t)oBase * KTOT;
    const __half* bG = g_Bf + (size_t)colBase * KTOT;

    int l16 = L & 15;
    unsigned chB = (unsigned)(L >> 4);
    unsigned fSwz = (unsigned)((l16 & 7) << 4);
    unsigned aRow[2], bRow[4];
#pragma unroll
    for (int mt = 0; mt < 2; mt++) aRow[mt] = (unsigned)((wm * 32 + mt * 16 + l16) * 128);
#pragma unroll
    for (int q = 0; q < 4; q++) bRow[q] = (unsigned)((wn * 64 + q * 16 + l16) * 128);

    float d[2][8][4];
#pragma unroll
    for (int mt = 0; mt < 2; mt++)
#pragma unroll
        for (int nt = 0; nt < 8; nt++)
#pragma unroll
            for (int qq = 0; qq < 4; qq++) d[mt][nt][qq] = 0.0f;

    // prologue: stages 0..2
#pragma unroll
    for (int st = 0; st < 3; st++) {
        issue_stage_B(sb0 + (unsigned)st * STAGEB, st * BK, t, bG);
        float4 av[8];
        ldgA(av, aG, st * BK, t);
        stsA(sb0 + (unsigned)st * STAGEB, av, t);
    }

    for (int kt = 0; kt < NIT; kt++) {
        asm volatile("cp.async.wait_group 2;" ::: "memory");
        __syncthreads();

        float4 av[8];
        bool has = (kt + 3) < NIT;
        if (has) {
            issue_stage_B(sb0 + (unsigned)((kt + 3) & 3) * STAGEB, (kt + 3) * BK, t, bG);
            ldgA(av, aG, (kt + 3) * BK, t);
        } else {
            cp_commit();
        }

        unsigned sb = sb0 + (unsigned)(kt & 3) * STAGEB;

#pragma unroll
        for (int ks = 0; ks < 4; ks++) {
            unsigned ch = ((unsigned)(ks * 2) + chB) << 4;
            unsigned chx = ch ^ fSwz;
            unsigned af[2][4], bf[4][4];
#pragma unroll
            for (int mt = 0; mt < 2; mt++)
                ldsm4(af[mt], sb + aRow[mt] + chx);
#pragma unroll
            for (int q = 0; q < 4; q++)
                ldsm4(bf[q], sb + 16384 + bRow[q] + chx);
#pragma unroll
            for (int mt = 0; mt < 2; mt++)
#pragma unroll
                for (int q = 0; q < 4; q++)
#pragma unroll
                    for (int h = 0; h < 2; h++) {
                        unsigned bv[2] = {bf[q][h], bf[q][h + 2]};
                        mma16816h(d[mt][q * 2 + h], af[mt], bv);
                    }
        }

        if (has)
            stsA(sb0 + (unsigned)((kt + 3) & 3) * STAGEB, av, t);
    }

    // ---- fused epilogue: stage tile to smem as [col][o], then LN to out ----
    asm volatile("cp.async.wait_group 0;" ::: "memory");
    __syncthreads();
    float* sD = reinterpret_cast<float*>(smem);

    int gid = L >> 2, tid4 = L & 3;
#pragma unroll
    for (int mt = 0; mt < 2; mt++) {
        int rl = wm * 32 + mt * 16 + gid;
#pragma unroll
        for (int nt = 0; nt < 8; nt++) {
            int cl = wn * 64 + nt * 8 + tid4 * 2;
            sD[cl * LDSD + rl]             = d[mt][nt][0];
            sD[(cl + 1) * LDSD + rl]       = d[mt][nt][1];
            sD[cl * LDSD + rl + 8]         = d[mt][nt][2];
            sD[(cl + 1) * LDSD + rl + 8]   = d[mt][nt][3];
        }
    }
    __syncthreads();

    float lg[HH], lb[HH];
#pragma unroll
    for (int h = 0; h < HH; h += 4) {
        float4 g4 = *(const float4*)&ln_g[h];
        float4 b4 = *(const float4*)&ln_b[h];
        lg[h] = g4.x; lg[h + 1] = g4.y; lg[h + 2] = g4.z; lg[h + 3] = g4.w;
        lb[h] = b4.x; lb[h + 1] = b4.y; lb[h + 2] = b4.z; lb[h + 3] = b4.w;
    }

#pragma unroll 1
    for (int it = 0; it < 4; it++) {
        int task = t + it * 256;          // 0..1023
        int ng = task & 7;                // 0..7
        int cl = task >> 3;               // 0..127
        int o0 = oBase + ng * 16;
        int colg = colBase + cl;
        size_t gbase = (size_t)colg * CC + o0;

        float v[HH];
#pragma unroll
        for (int h = 0; h < HH; h += 4) {
            float4 y = *(const float4*)&sD[cl * LDSD + ng * 16 + h];
            float4 cb = *(const float4*)&conv_b[o0 + h];
            float4 bm = *(const float4*)&bn_m[o0 + h];
            float4 bvr = *(const float4*)&bn_v[o0 + h];
            float4 bg = *(const float4*)&bn_g[o0 + h];
            float4 bb = *(const float4*)&bn_b[o0 + h];
            float4 xr = *(const float4*)&x[gbase + h];
            float yy[4] = {y.x, y.y, y.z, y.w};
            float cbv[4] = {cb.x, cb.y, cb.z, cb.w};
            float bmv[4] = {bm.x, bm.y, bm.z, bm.w};
            float bvv[4] = {bvr.x, bvr.y, bvr.z, bvr.w};
            float bgv[4] = {bg.x, bg.y, bg.z, bg.w};
            float bbv[4] = {bb.x, bb.y, bb.z, bb.w};
            float xv[4] = {xr.x, xr.y, xr.z, xr.w};
#pragma unroll
            for (int q = 0; q < 4; q++) {
                float val = yy[q] + cbv[q];
                val = (val - bmv[q]) * rsqrtf(bvv[q] + EPS) * bgv[q] + bbv[q];
                val = fmaxf(val, 0.0f);
                v[h + q] = val + xv[q];
            }
        }

        float mu = 0.0f;
#pragma unroll
        for (int h = 0; h < HH; h++) mu += v[h];
        mu *= (1.0f / HH);
        float var = 0.0f;
#pragma unroll
        for (int h = 0; h < HH; h++) { float dd = v[h] - mu; var += dd * dd; }
        var *= (1.0f / HH);
        float is = rsqrtf(var + EPS);

#pragma unroll
        for (int h = 0; h < HH; h += 4) {
            float4 o;
            o.x = (v[h]     - mu) * is * lg[h]     + lb[h];
            o.y = (v[h + 1] - mu) * is * lg[h + 1] + lb[h + 1];
            o.z = (v[h + 2] - mu) * is * lg[h + 2] + lb[h + 2];
            o.w = (v[h + 3] - mu) * is * lg[h + 3] + lb[h + 3];
            *(float4*)&out[gbase + h] = o;
        }
    }
}

// ---------------------------------------------------------------------------
extern "C" void kernel_launch(void* const* d_in, const int* in_sizes, int n_in,
                              void* d_out, int out_size) {
    const float* x      = (const float*)d_in[0];
    const float* adj    = (const float*)d_in[1];
    const float* W      = (const float*)d_in[2];
    const float* a1     = (const float*)d_in[3];
    const float* a2     = (const float*)d_in[4];
    const float* conv_w = (const float*)d_in[5];
    const float* conv_b = (const float*)d_in[6];
    const float* bn_g   = (const float*)d_in[7];
    const float* bn_b   = (const float*)d_in[8];
    const float* bn_m   = (const float*)d_in[9];
    const float* bn_v   = (const float*)d_in[10];
    const float* ln_g   = (const float*)d_in[11];
    const float* ln_b   = (const float*)d_in[12];
    float* out = (float*)d_out;

    cudaFuncSetAttribute(k_conv_mma, cudaFuncAttributeMaxDynamicSharedMemorySize, SMEM_DYN);

    k_gat<<<512, 256>>>(x, adj, W, a1, a2);
    k_conv_mma<<<dim3(4, 32), 256, SMEM_DYN>>>(conv_w, x, conv_b, bn_g, bn_b,
                                               bn_m, bn_v, ln_g, ln_b, out);
}

// round 14
// speedup vs baseline: 1.2648x; 1.2648x over previous
#include <cuda_runtime.h>
#include <cuda_fp16.h>
#include <cstdint>

// Problem constants
#define BB 8
#define SS 64
#define NN 256
#define FF 16
#define HH 16
#define CC 4096            // N*H  (= GEMM M)
#define COLS 512           // B*S  (= GEMM Ncol)
#define KTOT 12288         // C*3  (= GEMM K, tap-major: k = tap*4096 + c)
#define ALPHA 0.2f
#define EPS 1e-5f

// GEMM tiling (fp16 HMMA, single-term: D = A*B)
#define BK 64                       // fp16 K per stage (128B rows)
#define TILEB 16384                 // 128 rows x 64 fp16 x 2B, xor-swizzled
#define STAGEB 32768                // A, B tiles
#define NSTAGE 4
#define NIT (KTOT / BK)             // 192
#define SMEM_DYN (NSTAGE * STAGEB)  // 131072 (also covers epilogue tile)
#define LDSD 132                    // epilogue smem stride (floats)

#define GAT_BLOCKS 512
#define CVT_BLOCKS 16384            // 4096*1024 threads, 4 channels each

// ---------------- device scratch (no allocations allowed) -------------------
__device__ __half g_Af[(size_t)CC * KTOT];       // fp16 weights (tap-major K)
__device__ __half g_Bf[(size_t)COLS * KTOT];     // fp16 data (tap-major K)

// ---------------- PTX helpers ----------------------------------------------
__device__ __forceinline__ void cp16(unsigned dst, const void* src) {
    asm volatile("cp.async.cg.shared.global [%0], [%1], 16;" :: "r"(dst), "l"(src) : "memory");
}
__device__ __forceinline__ void cp_commit() {
    asm volatile("cp.async.commit_group;" ::: "memory");
}
__device__ __forceinline__ void ldsm4(unsigned* r, unsigned addr) {
    asm volatile("ldmatrix.sync.aligned.m8n8.x4.shared.b16 {%0,%1,%2,%3}, [%4];"
                 : "=r"(r[0]), "=r"(r[1]), "=r"(r[2]), "=r"(r[3]) : "r"(addr));
}
__device__ __forceinline__ void mma16816h(float* d, const unsigned* a, const unsigned* b) {
    asm volatile(
        "mma.sync.aligned.m16n8k16.row.col.f32.f16.f16.f32 "
        "{%0,%1,%2,%3}, {%4,%5,%6,%7}, {%8,%9}, {%0,%1,%2,%3};"
        : "+f"(d[0]), "+f"(d[1]), "+f"(d[2]), "+f"(d[3])
        : "r"(a[0]), "r"(a[1]), "r"(a[2]), "r"(a[3]), "r"(b[0]), "r"(b[1]));
}

// ---------------------------------------------------------------------------
// Fat kernel: blocks [0,512) = GAT (inline mask ballot + wh + softmax +
// spatial + B scatter); blocks [512, 512+16384) = weight fp32->fp16 tap-major.
// ---------------------------------------------------------------------------
__device__ void gat_body(int bs, const float* __restrict__ x,
                         const float* __restrict__ adj,
                         const float* __restrict__ W,
                         const float* __restrict__ a1v,
                         const float* __restrict__ a2v) {
    __shared__ float    sW[FF * HH];
    __shared__ float    sa1[HH], sa2[HH];
    __shared__ float    sWh[NN * HH];
    __shared__ float    sf2[NN];
    __shared__ unsigned smask[NN * 8];

    int t = threadIdx.x;
    int wid = t >> 5, lane = t & 31;

    sW[t] = W[t];
    if (t < HH) { sa1[t] = a1v[t]; sa2[t] = a2v[t]; }

    // inline mask ballot: warp wid covers all idx ≡ wid (mod 8); x4 unroll for MLP
#pragma unroll 1
    for (int idx = wid; idx < NN * 8; idx += 32) {
        float v0 = adj[(idx >> 3) * NN + (idx & 7) * 32 + lane];
        float v1 = adj[((idx + 8) >> 3) * NN + ((idx + 8) & 7) * 32 + lane];
        float v2 = adj[((idx + 16) >> 3) * NN + ((idx + 16) & 7) * 32 + lane];
        float v3 = adj[((idx + 24) >> 3) * NN + ((idx + 24) & 7) * 32 + lane];
        unsigned m0 = __ballot_sync(0xffffffffu, v0 > 0.0f);
        unsigned m1 = __ballot_sync(0xffffffffu, v1 > 0.0f);
        unsigned m2 = __ballot_sync(0xffffffffu, v2 > 0.0f);
        unsigned m3 = __ballot_sync(0xffffffffu, v3 > 0.0f);
        if (lane == 0) {
            smask[idx] = m0; smask[idx + 8] = m1;
            smask[idx + 16] = m2; smask[idx + 24] = m3;
        }
    }
    __syncthreads();

    // ---- Wh = x @ W ; f1, f2 ----
    const float* xr = x + (size_t)(bs * NN + t) * FF;
    float xv[FF];
#pragma unroll
    for (int f = 0; f < FF; f += 4) {
        float4 v = *(const float4*)(xr + f);
        xv[f] = v.x; xv[f + 1] = v.y; xv[f + 2] = v.z; xv[f + 3] = v.w;
    }
    float wh[HH];
#pragma unroll
    for (int h = 0; h < HH; h++) wh[h] = 0.0f;
#pragma unroll
    for (int f = 0; f < FF; f++)
#pragma unroll
        for (int h = 0; h < HH; h++) wh[h] += xv[f] * sW[f * HH + h];

    float f1i = 0.0f, f2i = 0.0f;
#pragma unroll
    for (int h = 0; h < HH; h++) { f1i += wh[h] * sa1[h]; f2i += wh[h] * sa2[h]; }

#pragma unroll
    for (int h = 0; h < HH; h++) sWh[t * HH + h] = wh[h];
    sf2[t] = f2i;
    __syncthreads();

    // ---- masked softmax: pass 1 max ----
    float m = -1e30f;
#pragma unroll 1
    for (int jw = 0; jw < 8; jw++) {
        unsigned wd = smask[t * 8 + jw];
#pragma unroll
        for (int bit = 0; bit < 32; bit++) {
            float e = f1i + sf2[jw * 32 + bit];
            e = e > 0.0f ? e : ALPHA * e;
            if ((wd >> bit) & 1u) m = fmaxf(m, e);
        }
    }

    // ---- pass 2: exp/sum + weighted accumulate ----
    float sum = 0.0f;
    float acc[HH];
#pragma unroll
    for (int h = 0; h < HH; h++) acc[h] = 0.0f;

#pragma unroll 1
    for (int jw = 0; jw < 8; jw++) {
        unsigned wd = smask[t * 8 + jw];
#pragma unroll
        for (int bit = 0; bit < 32; bit++) {
            int j = jw * 32 + bit;
            float e = f1i + sf2[j];
            e = e > 0.0f ? e : ALPHA * e;
            float w = ((wd >> bit) & 1u) ? __expf(e - m) : 0.0f;
            sum += w;
#pragma unroll
            for (int h = 0; h < HH; h++) acc[h] += w * sWh[j * HH + h];
        }
    }

    float inv = 1.0f / sum;
    __half hv[16];
#pragma unroll
    for (int h = 0; h < HH; h++) hv[h] = __float2half_rn(acc[h] * inv);
    const uint4 u0 = *reinterpret_cast<uint4*>(hv);
    const uint4 u1 = *reinterpret_cast<uint4*>(hv + 8);

    // ---- scatter into tap-major B: k = tap*4096 + c, c in [t*16, t*16+16) ----
    int s = bs & 63;
    int c0 = t * HH;
    {   // own tap 1
        uint4* p = reinterpret_cast<uint4*>(g_Bf + (size_t)bs * KTOT + 4096 + c0);
        p[0] = u0; p[1] = u1;
    }
    if (s < 63) {   // tap 0 of col+1
        uint4* p = reinterpret_cast<uint4*>(g_Bf + (size_t)(bs + 1) * KTOT + c0);
        p[0] = u0; p[1] = u1;
    }
    if (s > 0) {    // tap 2 of col-1
        uint4* p = reinterpret_cast<uint4*>(g_Bf + (size_t)(bs - 1) * KTOT + 8192 + c0);
        p[0] = u0; p[1] = u1;
    }
    const uint4 z = make_uint4(0, 0, 0, 0);
    if (s == 0) {
        uint4* p = reinterpret_cast<uint4*>(g_Bf + (size_t)bs * KTOT + c0);
        p[0] = z; p[1] = z;
    }
    if (s == 63) {
        uint4* p = reinterpret_cast<uint4*>(g_Bf + (size_t)bs * KTOT + 8192 + c0);
        p[0] = z; p[1] = z;
    }
}

__device__ void cvt_body(int cb, const float* __restrict__ w) {
    int g = cb * 256 + threadIdx.x;        // 0 .. 4096*1024-1
    int o = g >> 10;
    int c0 = (g & 1023) * 4;
    const float* src = w + (size_t)o * KTOT + (size_t)c0 * 3;
    float4 v0 = *(const float4*)(src);
    float4 v1 = *(const float4*)(src + 4);
    float4 v2 = *(const float4*)(src + 8);
    float f[12] = {v0.x, v0.y, v0.z, v0.w, v1.x, v1.y, v1.z, v1.w,
                   v2.x, v2.y, v2.z, v2.w};
    __half hp[3][4];
#pragma unroll
    for (int i = 0; i < 4; i++) {
#pragma unroll
        for (int tap = 0; tap < 3; tap++)
            hp[tap][i] = __float2half_rn(f[i * 3 + tap]);
    }
    size_t base = (size_t)o * KTOT + c0;
#pragma unroll
    for (int tap = 0; tap < 3; tap++)
        *reinterpret_cast<uint2*>(g_Af + base + tap * 4096) =
            *reinterpret_cast<uint2*>(hp[tap]);
}

__global__ __launch_bounds__(256) void k_fat(const float* __restrict__ x,
                                             const float* __restrict__ adj,
                                             const float* __restrict__ W,
                                             const float* __restrict__ a1v,
                                             const float* __restrict__ a2v,
                                             const float* __restrict__ w) {
    if (blockIdx.x < GAT_BLOCKS)
        gat_body(blockIdx.x, x, adj, W, a1v, a2v);
    else
        cvt_body(blockIdx.x - GAT_BLOCKS, w);
}

// ---------------------------------------------------------------------------
// Conv GEMM + fused epilogue. D[o][col] = A[o][:].B[col][:], then
// bias+BN+ReLU+residual+LayerNorm straight to out.
// 128x128 CTA tile, BK=64, 4 stages, 8 warps (4M x 2N), warp tile m32n64.
// ---------------------------------------------------------------------------
__device__ __forceinline__ void issue_stage(unsigned sbs, int kb, int t,
                                            const __half* aG, const __half* bG) {
    int row = t >> 1;                   // 0..127
    int h2 = t & 1;
    unsigned rowB = (unsigned)(row * 128);
    unsigned swz = (unsigned)((row & 7) << 4);
    size_t go = (size_t)row * KTOT + kb;
#pragma unroll
    for (int j = 0; j < 4; j++) {
        int cidx = j * 2 + h2;
        unsigned dsw = rowB + (((unsigned)(cidx * 16)) ^ swz);
        size_t gs = go + cidx * 8;
        cp16(sbs + dsw,          aG + gs);
        cp16(sbs + 16384 + dsw,  bG + gs);
    }
    cp_commit();
}

__global__ __launch_bounds__(256, 1) void k_conv_mma(
        const float* __restrict__ x,
        const float* __restrict__ conv_b,
        const float* __restrict__ bn_g, const float* __restrict__ bn_b,
        const float* __restrict__ bn_m, const float* __restrict__ bn_v,
        const float* __restrict__ ln_g, const float* __restrict__ ln_b,
        float* __restrict__ out) {
    extern __shared__ __align__(1024) char smem[];
    unsigned sb0 = (unsigned)__cvta_generic_to_shared(smem);

    int t = threadIdx.x;
    int wid = t >> 5;
    int L = t & 31;
    int wm = wid & 3;          // 4 warps along M (o)
    int wn = wid >> 2;         // 2 warps along N (col)
    int colBase = blockIdx.x * 128;
    int oBase = blockIdx.y * 128;

    const __half* aG = g_Af + (size_t)oBase * KTOT;
    const __half* bG = g_Bf + (size_t)colBase * KTOT;

    int l16 = L & 15;
    unsigned chB = (unsigned)(L >> 4);
    unsigned fSwz = (unsigned)((l16 & 7) << 4);
    unsigned aRow[2], bRow[4];
#pragma unroll
    for (int mt = 0; mt < 2; mt++) aRow[mt] = (unsigned)((wm * 32 + mt * 16 + l16) * 128);
#pragma unroll
    for (int q = 0; q < 4; q++) bRow[q] = (unsigned)((wn * 64 + q * 16 + l16) * 128);

    float d[2][8][4];
#pragma unroll
    for (int mt = 0; mt < 2; mt++)
#pragma unroll
        for (int nt = 0; nt < 8; nt++)
#pragma unroll
            for (int qq = 0; qq < 4; qq++) d[mt][nt][qq] = 0.0f;

    issue_stage(sb0, 0, t, aG, bG);
    issue_stage(sb0 + STAGEB, BK, t, aG, bG);
    issue_stage(sb0 + 2 * STAGEB, 2 * BK, t, aG, bG);

    for (int kt = 0; kt < NIT; kt++) {
        asm volatile("cp.async.wait_group 2;" ::: "memory");
        __syncthreads();

        if (kt + 3 < NIT)
            issue_stage(sb0 + (unsigned)((kt + 3) & 3) * STAGEB, (kt + 3) * BK,
                        t, aG, bG);
        else
            cp_commit();

        unsigned sb = sb0 + (unsigned)(kt & 3) * STAGEB;

#pragma unroll
        for (int ks = 0; ks < 4; ks++) {
            unsigned ch = ((unsigned)(ks * 2) + chB) << 4;
            unsigned chx = ch ^ fSwz;
            unsigned af[2][4], bf[4][4];
#pragma unroll
            for (int mt = 0; mt < 2; mt++)
                ldsm4(af[mt], sb + aRow[mt] + chx);
#pragma unroll
            for (int q = 0; q < 4; q++)
                ldsm4(bf[q], sb + 16384 + bRow[q] + chx);
#pragma unroll
            for (int mt = 0; mt < 2; mt++)
#pragma unroll
                for (int q = 0; q < 4; q++)
#pragma unroll
                    for (int h = 0; h < 2; h++) {
                        unsigned bv[2] = {bf[q][h], bf[q][h + 2]};
                        mma16816h(d[mt][q * 2 + h], af[mt], bv);
                    }
        }
    }

    // ---- fused epilogue: stage tile to smem as [col][o], then LN to out ----
    asm volatile("cp.async.wait_group 0;" ::: "memory");
    __syncthreads();
    float* sD = reinterpret_cast<float*>(smem);

    int gid = L >> 2, tid4 = L & 3;
#pragma unroll
    for (int mt = 0; mt < 2; mt++) {
        int rl = wm * 32 + mt * 16 + gid;
#pragma unroll
        for (int nt = 0; nt < 8; nt++) {
            int cl = wn * 64 + nt * 8 + tid4 * 2;
            sD[cl * LDSD + rl]             = d[mt][nt][0];
            sD[(cl + 1) * LDSD + rl]       = d[mt][nt][1];
            sD[cl * LDSD + rl + 8]         = d[mt][nt][2];
            sD[(cl + 1) * LDSD + rl + 8]   = d[mt][nt][3];
        }
    }
    __syncthreads();

    float lg[HH], lb[HH];
#pragma unroll
    for (int h = 0; h < HH; h += 4) {
        float4 g4 = *(const float4*)&ln_g[h];
        float4 b4 = *(const float4*)&ln_b[h];
        lg[h] = g4.x; lg[h + 1] = g4.y; lg[h + 2] = g4.z; lg[h + 3] = g4.w;
        lb[h] = b4.x; lb[h + 1] = b4.y; lb[h + 2] = b4.z; lb[h + 3] = b4.w;
    }

#pragma unroll 1
    for (int it = 0; it < 4; it++) {
        int task = t + it * 256;          // 0..1023
        int ng = task & 7;                // 0..7
        int cl = task >> 3;               // 0..127
        int o0 = oBase + ng * 16;
        int colg = colBase + cl;
        size_t gbase = (size_t)colg * CC + o0;

        float v[HH];
#pragma unroll
        for (int h = 0; h < HH; h += 4) {
            float4 y = *(const float4*)&sD[cl * LDSD + ng * 16 + h];
            float4 cb = *(const float4*)&conv_b[o0 + h];
            float4 bm = *(const float4*)&bn_m[o0 + h];
            float4 bvr = *(const float4*)&bn_v[o0 + h];
            float4 bg = *(const float4*)&bn_g[o0 + h];
            float4 bb = *(const float4*)&bn_b[o0 + h];
            float4 xr = *(const float4*)&x[gbase + h];
            float yy[4] = {y.x, y.y, y.z, y.w};
            float cbv[4] = {cb.x, cb.y, cb.z, cb.w};
            float bmv[4] = {bm.x, bm.y, bm.z, bm.w};
            float bvv[4] = {bvr.x, bvr.y, bvr.z, bvr.w};
            float bgv[4] = {bg.x, bg.y, bg.z, bg.w};
            float bbv[4] = {bb.x, bb.y, bb.z, bb.w};
            float xv[4] = {xr.x, xr.y, xr.z, xr.w};
#pragma unroll
            for (int q = 0; q < 4; q++) {
                float val = yy[q] + cbv[q];
                val = (val - bmv[q]) * rsqrtf(bvv[q] + EPS) * bgv[q] + bbv[q];
                val = fmaxf(val, 0.0f);
                v[h + q] = val + xv[q];
            }
        }

        float mu = 0.0f;
#pragma unroll
        for (int h = 0; h < HH; h++) mu += v[h];
        mu *= (1.0f / HH);
        float var = 0.0f;
#pragma unroll
        for (int h = 0; h < HH; h++) { float dd = v[h] - mu; var += dd * dd; }
        var *= (1.0f / HH);
        float is = rsqrtf(var + EPS);

#pragma unroll
        for (int h = 0; h < HH; h += 4) {
            float4 o;
            o.x = (v[h]     - mu) * is * lg[h]     + lb[h];
            o.y = (v[h + 1] - mu) * is * lg[h + 1] + lb[h + 1];
            o.z = (v[h + 2] - mu) * is * lg[h + 2] + lb[h + 2];
            o.w = (v[h + 3] - mu) * is * lg[h + 3] + lb[h + 3];
            *(float4*)&out[gbase + h] = o;
        }
    }
}

// ---------------------------------------------------------------------------
extern "C" void kernel_launch(void* const* d_in, const int* in_sizes, int n_in,
                              void* d_out, int out_size) {
    const float* x      = (const float*)d_in[0];
    const float* adj    = (const float*)d_in[1];
    const float* W      = (const float*)d_in[2];
    const float* a1     = (const float*)d_in[3];
    const float* a2     = (const float*)d_in[4];
    const float* conv_w = (const float*)d_in[5];
    const float* conv_b = (const float*)d_in[6];
    const float* bn_g   = (const float*)d_in[7];
    const float* bn_b   = (const float*)d_in[8];
    const float* bn_m   = (const float*)d_in[9];
    const float* bn_v   = (const float*)d_in[10];
    const float* ln_g   = (const float*)d_in[11];
    const float* ln_b   = (const float*)d_in[12];
    float* out = (float*)d_out;

    cudaFuncSetAttribute(k_conv_mma, cudaFuncAttributeMaxDynamicSharedMemorySize, SMEM_DYN);

    k_fat<<<GAT_BLOCKS + CVT_BLOCKS, 256>>>(x, adj, W, a1, a2, conv_w);
    k_conv_mma<<<dim3(4, 32), 256, SMEM_DYN>>>(x, conv_b, bn_g, bn_b,
                                               bn_m, bn_v, ln_g, ln_b, out);
}

// round 15
// speedup vs baseline: 1.6197x; 1.2806x over previous
#include <cuda_runtime.h>
#include <cuda_fp16.h>
#include <cstdint>

// Problem constants
#define BB 8
#define SS 64
#define NN 256
#define FF 16
#define HH 16
#define CC 4096            // N*H  (= GEMM M)
#define COLS 512           // B*S  (= GEMM Ncol)
#define KTOT 12288         // C*3  (= GEMM K, tap-major: k = tap*4096 + c)
#define ALPHA 0.2f
#define EPS 1e-5f

// GEMM tiling (fp16 HMMA, single-term: D = A*B)
#define BK 64                       // fp16 K per stage (128B rows)
#define TILEB 16384                 // 128 rows x 64 fp16 x 2B, xor-swizzled
#define STAGEB 32768                // A, B tiles
#define NSTAGE 4
#define NIT (KTOT / BK)             // 192
#define SMEM_DYN (NSTAGE * STAGEB)  // 131072 (also covers epilogue tile)
#define LDSD 132                    // epilogue smem stride (floats)

#define GAT_BLOCKS 512
#define CVT_BLOCKS 16384            // 4096*1024 threads, 4 channels each

// ---------------- device scratch (no allocations allowed) -------------------
__device__ unsigned g_mask[NN * 8];
__device__ __half   g_Af[(size_t)CC * KTOT];       // fp16 weights (tap-major K)
__device__ __half   g_Bf[(size_t)COLS * KTOT];     // fp16 data (tap-major K)

// ---------------- PTX helpers ----------------------------------------------
__device__ __forceinline__ void cp16(unsigned dst, const void* src) {
    asm volatile("cp.async.cg.shared.global [%0], [%1], 16;" :: "r"(dst), "l"(src) : "memory");
}
__device__ __forceinline__ void cp_commit() {
    asm volatile("cp.async.commit_group;" ::: "memory");
}
__device__ __forceinline__ void ldsm4(unsigned* r, unsigned addr) {
    asm volatile("ldmatrix.sync.aligned.m8n8.x4.shared.b16 {%0,%1,%2,%3}, [%4];"
                 : "=r"(r[0]), "=r"(r[1]), "=r"(r[2]), "=r"(r[3]) : "r"(addr));
}
__device__ __forceinline__ void mma16816h(float* d, const unsigned* a, const unsigned* b) {
    asm volatile(
        "mma.sync.aligned.m16n8k16.row.col.f32.f16.f16.f32 "
        "{%0,%1,%2,%3}, {%4,%5,%6,%7}, {%8,%9}, {%0,%1,%2,%3};"
        : "+f"(d[0]), "+f"(d[1]), "+f"(d[2]), "+f"(d[3])
        : "r"(a[0]), "r"(a[1]), "r"(a[2]), "r"(a[3]), "r"(b[0]), "r"(b[1]));
}

// ---------------------------------------------------------------------------
// Kernel 0: adjacency bitmask, one ballot per word (2048 warps)
// ---------------------------------------------------------------------------
__global__ void k_mask(const float* __restrict__ adj) {
    int gw = (blockIdx.x * 256 + threadIdx.x) >> 5;   // global warp 0..2047
    int lane = threadIdx.x & 31;
    int i = gw >> 3, w = gw & 7;
    float v = adj[i * NN + w * 32 + lane];
    unsigned m = __ballot_sync(0xffffffffu, v > 0.0f);
    if (lane == 0) g_mask[gw] = m;
}

// ---------------------------------------------------------------------------
// Fat kernel: blocks [0,512) = GAT; blocks [512, 512+16384) = weight convert.
// ---------------------------------------------------------------------------
__device__ void gat_body(int bs, const float* __restrict__ x,
                         const float* __restrict__ W,
                         const float* __restrict__ a1v,
                         const float* __restrict__ a2v) {
    __shared__ float    sW[FF * HH];
    __shared__ float    sa1[HH], sa2[HH];
    __shared__ float    sWh[NN * HH];
    __shared__ float    sf2[NN];
    __shared__ unsigned smask[NN * 8];

    int t = threadIdx.x;
    sW[t] = W[t];
    if (t < HH) { sa1[t] = a1v[t]; sa2[t] = a2v[t]; }
    for (int idx = t; idx < NN * 8; idx += 256) smask[idx] = g_mask[idx];
    __syncthreads();

    const float* xr = x + (size_t)(bs * NN + t) * FF;
    float xv[FF];
#pragma unroll
    for (int f = 0; f < FF; f += 4) {
        float4 v = *(const float4*)(xr + f);
        xv[f] = v.x; xv[f + 1] = v.y; xv[f + 2] = v.z; xv[f + 3] = v.w;
    }
    float wh[HH];
#pragma unroll
    for (int h = 0; h < HH; h++) wh[h] = 0.0f;
#pragma unroll
    for (int f = 0; f < FF; f++)
#pragma unroll
        for (int h = 0; h < HH; h++) wh[h] += xv[f] * sW[f * HH + h];

    float f1i = 0.0f, f2i = 0.0f;
#pragma unroll
    for (int h = 0; h < HH; h++) { f1i += wh[h] * sa1[h]; f2i += wh[h] * sa2[h]; }

#pragma unroll
    for (int h = 0; h < HH; h++) sWh[t * HH + h] = wh[h];
    sf2[t] = f2i;
    __syncthreads();

    float m = -1e30f;
#pragma unroll 1
    for (int jw = 0; jw < 8; jw++) {
        unsigned wd = smask[t * 8 + jw];
#pragma unroll
        for (int bit = 0; bit < 32; bit++) {
            float e = f1i + sf2[jw * 32 + bit];
            e = e > 0.0f ? e : ALPHA * e;
            if ((wd >> bit) & 1u) m = fmaxf(m, e);
        }
    }

    float sum = 0.0f;
    float acc[HH];
#pragma unroll
    for (int h = 0; h < HH; h++) acc[h] = 0.0f;

#pragma unroll 1
    for (int jw = 0; jw < 8; jw++) {
        unsigned wd = smask[t * 8 + jw];
#pragma unroll
        for (int bit = 0; bit < 32; bit++) {
            int j = jw * 32 + bit;
            float e = f1i + sf2[j];
            e = e > 0.0f ? e : ALPHA * e;
            float w = ((wd >> bit) & 1u) ? __expf(e - m) : 0.0f;
            sum += w;
#pragma unroll
            for (int h = 0; h < HH; h++) acc[h] += w * sWh[j * HH + h];
        }
    }

    float inv = 1.0f / sum;
    __half hv[16];
#pragma unroll
    for (int h = 0; h < HH; h++) hv[h] = __float2half_rn(acc[h] * inv);
    const uint4 u0 = *reinterpret_cast<uint4*>(hv);
    const uint4 u1 = *reinterpret_cast<uint4*>(hv + 8);

    int s = bs & 63;
    int c0 = t * HH;
    {   // own tap 1
        uint4* p = reinterpret_cast<uint4*>(g_Bf + (size_t)bs * KTOT + 4096 + c0);
        p[0] = u0; p[1] = u1;
    }
    if (s < 63) {   // tap 0 of col+1
        uint4* p = reinterpret_cast<uint4*>(g_Bf + (size_t)(bs + 1) * KTOT + c0);
        p[0] = u0; p[1] = u1;
    }
    if (s > 0) {    // tap 2 of col-1
        uint4* p = reinterpret_cast<uint4*>(g_Bf + (size_t)(bs - 1) * KTOT + 8192 + c0);
        p[0] = u0; p[1] = u1;
    }
    const uint4 z = make_uint4(0, 0, 0, 0);
    if (s == 0) {
        uint4* p = reinterpret_cast<uint4*>(g_Bf + (size_t)bs * KTOT + c0);
        p[0] = z; p[1] = z;
    }
    if (s == 63) {
        uint4* p = reinterpret_cast<uint4*>(g_Bf + (size_t)bs * KTOT + 8192 + c0);
        p[0] = z; p[1] = z;
    }
}

__device__ void cvt_body(int cb, const float* __restrict__ w) {
    int g = cb * 256 + threadIdx.x;        // 0 .. 4096*1024-1
    int o = g >> 10;
    int c0 = (g & 1023) * 4;
    const float* src = w + (size_t)o * KTOT + (size_t)c0 * 3;
    float4 v0 = *(const float4*)(src);
    float4 v1 = *(const float4*)(src + 4);
    float4 v2 = *(const float4*)(src + 8);
    float f[12] = {v0.x, v0.y, v0.z, v0.w, v1.x, v1.y, v1.z, v1.w,
                   v2.x, v2.y, v2.z, v2.w};
    __half hp[3][4];
#pragma unroll
    for (int i = 0; i < 4; i++) {
#pragma unroll
        for (int tap = 0; tap < 3; tap++)
            hp[tap][i] = __float2half_rn(f[i * 3 + tap]);
    }
    size_t base = (size_t)o * KTOT + c0;
#pragma unroll
    for (int tap = 0; tap < 3; tap++)
        *reinterpret_cast<uint2*>(g_Af + base + tap * 4096) =
            *reinterpret_cast<uint2*>(hp[tap]);
}

__global__ __launch_bounds__(256) void k_fat(const float* __restrict__ x,
                                             const float* __restrict__ W,
                                             const float* __restrict__ a1v,
                                             const float* __restrict__ a2v,
                                             const float* __restrict__ w) {
    if (blockIdx.x < GAT_BLOCKS)
        gat_body(blockIdx.x, x, W, a1v, a2v);
    else
        cvt_body(blockIdx.x - GAT_BLOCKS, w);
}

// ---------------------------------------------------------------------------
// Conv GEMM + fused epilogue. 512 threads, 16 warps (4M x 4N), warp m32n32.
// 128x128 CTA tile, BK=64, 4 stages.
// ---------------------------------------------------------------------------
__device__ __forceinline__ void issue_stage(unsigned sbs, int kb, int t,
                                            const __half* aG, const __half* bG) {
    int row = t >> 2;                   // 0..127 (4 threads per row)
    int quad = t & 3;
    unsigned rowB = (unsigned)(row * 128);
    unsigned swz = (unsigned)((row & 7) << 4);
    size_t go = (size_t)row * KTOT + kb;
#pragma unroll
    for (int j = 0; j < 2; j++) {
        int cidx = quad * 2 + j;        // 0..7
        unsigned dsw = rowB + (((unsigned)(cidx * 16)) ^ swz);
        size_t gs = go + cidx * 8;
        cp16(sbs + dsw,          aG + gs);
        cp16(sbs + 16384 + dsw,  bG + gs);
    }
    cp_commit();
}

__global__ __launch_bounds__(512, 1) void k_conv_mma(
        const float* __restrict__ x,
        const float* __restrict__ conv_b,
        const float* __restrict__ bn_g, const float* __restrict__ bn_b,
        const float* __restrict__ bn_m, const float* __restrict__ bn_v,
        const float* __restrict__ ln_g, const float* __restrict__ ln_b,
        float* __restrict__ out) {
    extern __shared__ __align__(1024) char smem[];
    unsigned sb0 = (unsigned)__cvta_generic_to_shared(smem);

    int t = threadIdx.x;
    int wid = t >> 5;
    int L = t & 31;
    int wm = wid & 3;          // 4 warps along M (o)
    int wn = wid >> 2;         // 4 warps along N (col)
    int colBase = blockIdx.x * 128;
    int oBase = blockIdx.y * 128;

    const __half* aG = g_Af + (size_t)oBase * KTOT;
    const __half* bG = g_Bf + (size_t)colBase * KTOT;

    int l16 = L & 15;
    unsigned chB = (unsigned)(L >> 4);
    unsigned fSwz = (unsigned)((l16 & 7) << 4);
    unsigned aRow[2], bRow[2];
#pragma unroll
    for (int mt = 0; mt < 2; mt++) aRow[mt] = (unsigned)((wm * 32 + mt * 16 + l16) * 128);
#pragma unroll
    for (int q = 0; q < 2; q++) bRow[q] = (unsigned)((wn * 32 + q * 16 + l16) * 128);

    float d[2][4][4];
#pragma unroll
    for (int mt = 0; mt < 2; mt++)
#pragma unroll
        for (int nt = 0; nt < 4; nt++)
#pragma unroll
            for (int qq = 0; qq < 4; qq++) d[mt][nt][qq] = 0.0f;

    issue_stage(sb0, 0, t, aG, bG);
    issue_stage(sb0 + STAGEB, BK, t, aG, bG);
    issue_stage(sb0 + 2 * STAGEB, 2 * BK, t, aG, bG);

    for (int kt = 0; kt < NIT; kt++) {
        asm volatile("cp.async.wait_group 2;" ::: "memory");
        __syncthreads();

        if (kt + 3 < NIT)
            issue_stage(sb0 + (unsigned)((kt + 3) & 3) * STAGEB, (kt + 3) * BK,
                        t, aG, bG);
        else
            cp_commit();

        unsigned sb = sb0 + (unsigned)(kt & 3) * STAGEB;

#pragma unroll
        for (int ks = 0; ks < 4; ks++) {
            unsigned ch = ((unsigned)(ks * 2) + chB) << 4;
            unsigned chx = ch ^ fSwz;
            unsigned af[2][4], bf[2][4];
#pragma unroll
            for (int mt = 0; mt < 2; mt++)
                ldsm4(af[mt], sb + aRow[mt] + chx);
#pragma unroll
            for (int q = 0; q < 2; q++)
                ldsm4(bf[q], sb + 16384 + bRow[q] + chx);
#pragma unroll
            for (int mt = 0; mt < 2; mt++)
#pragma unroll
                for (int q = 0; q < 2; q++)
#pragma unroll
                    for (int h = 0; h < 2; h++) {
                        unsigned bv[2] = {bf[q][h], bf[q][h + 2]};
                        mma16816h(d[mt][q * 2 + h], af[mt], bv);
                    }
        }
    }

    // ---- fused epilogue: stage tile to smem as [col][o], then LN to out ----
    asm volatile("cp.async.wait_group 0;" ::: "memory");
    __syncthreads();
    float* sD = reinterpret_cast<float*>(smem);

    int gid = L >> 2, tid4 = L & 3;
#pragma unroll
    for (int mt = 0; mt < 2; mt++) {
        int rl = wm * 32 + mt * 16 + gid;
#pragma unroll
        for (int nt = 0; nt < 4; nt++) {
            int cl = wn * 32 + nt * 8 + tid4 * 2;
            sD[cl * LDSD + rl]             = d[mt][nt][0];
            sD[(cl + 1) * LDSD + rl]       = d[mt][nt][1];
            sD[cl * LDSD + rl + 8]         = d[mt][nt][2];
            sD[(cl + 1) * LDSD + rl + 8]   = d[mt][nt][3];
        }
    }
    __syncthreads();

    float lg[HH], lb[HH];
#pragma unroll
    for (int h = 0; h < HH; h += 4) {
        float4 g4 = *(const float4*)&ln_g[h];
        float4 b4 = *(const float4*)&ln_b[h];
        lg[h] = g4.x; lg[h + 1] = g4.y; lg[h + 2] = g4.z; lg[h + 3] = g4.w;
        lb[h] = b4.x; lb[h + 1] = b4.y; lb[h + 2] = b4.z; lb[h + 3] = b4.w;
    }

#pragma unroll 1
    for (int it = 0; it < 2; it++) {
        int task = t + it * 512;          // 0..1023
        int ng = task & 7;                // 0..7
        int cl = task >> 3;               // 0..127
        int o0 = oBase + ng * 16;
        int colg = colBase + cl;
        size_t gbase = (size_t)colg * CC + o0;

        float v[HH];
#pragma unroll
        for (int h = 0; h < HH; h += 4) {
            float4 y = *(const float4*)&sD[cl * LDSD + ng * 16 + h];
            float4 cb = *(const float4*)&conv_b[o0 + h];
            float4 bm = *(const float4*)&bn_m[o0 + h];
            float4 bvr = *(const float4*)&bn_v[o0 + h];
            float4 bg = *(const float4*)&bn_g[o0 + h];
            float4 bb = *(const float4*)&bn_b[o0 + h];
            float4 xr = *(const float4*)&x[gbase + h];
            float yy[4] = {y.x, y.y, y.z, y.w};
            float cbv[4] = {cb.x, cb.y, cb.z, cb.w};
            float bmv[4] = {bm.x, bm.y, bm.z, bm.w};
            float bvv[4] = {bvr.x, bvr.y, bvr.z, bvr.w};
            float bgv[4] = {bg.x, bg.y, bg.z, bg.w};
            float bbv[4] = {bb.x, bb.y, bb.z, bb.w};
            float xv[4] = {xr.x, xr.y, xr.z, xr.w};
#pragma unroll
            for (int q = 0; q < 4; q++) {
                float val = yy[q] + cbv[q];
                val = (val - bmv[q]) * rsqrtf(bvv[q] + EPS) * bgv[q] + bbv[q];
                val = fmaxf(val, 0.0f);
                v[h + q] = val + xv[q];
            }
        }

        float mu = 0.0f;
#pragma unroll
        for (int h = 0; h < HH; h++) mu += v[h];
        mu *= (1.0f / HH);
        float var = 0.0f;
#pragma unroll
        for (int h = 0; h < HH; h++) { float dd = v[h] - mu; var += dd * dd; }
        var *= (1.0f / HH);
        float is = rsqrtf(var + EPS);

#pragma unroll
        for (int h = 0; h < HH; h += 4) {
            float4 o;
            o.x = (v[h]     - mu) * is * lg[h]     + lb[h];
            o.y = (v[h + 1] - mu) * is * lg[h + 1] + lb[h + 1];
            o.z = (v[h + 2] - mu) * is * lg[h + 2] + lb[h + 2];
            o.w = (v[h + 3] - mu) * is * lg[h + 3] + lb[h + 3];
            *(float4*)&out[gbase + h] = o;
        }
    }
}

// ---------------------------------------------------------------------------
extern "C" void kernel_launch(void* const* d_in, const int* in_sizes, int n_in,
                              void* d_out, int out_size) {
    const float* x      = (const float*)d_in[0];
    const float* adj    = (const float*)d_in[1];
    const float* W      = (const float*)d_in[2];
    const float* a1     = (const float*)d_in[3];
    const float* a2     = (const float*)d_in[4];
    const float* conv_w = (const float*)d_in[5];
    const float* conv_b = (const float*)d_in[6];
    const float* bn_g   = (const float*)d_in[7];
    const float* bn_b   = (const float*)d_in[8];
    const float* bn_m   = (const float*)d_in[9];
    const float* bn_v   = (const float*)d_in[10];
    const float* ln_g   = (const float*)d_in[11];
    const float* ln_b   = (const float*)d_in[12];
    float* out = (float*)d_out;

    cudaFuncSetAttribute(k_conv_mma, cudaFuncAttributeMaxDynamicSharedMemorySize, SMEM_DYN);

    k_mask<<<256, 256>>>(adj);
    k_fat<<<GAT_BLOCKS + CVT_BLOCKS, 256>>>(x, W, a1, a2, conv_w);
    k_conv_mma<<<dim3(4, 32), 512, SMEM_DYN>>>(x, conv_b, bn_g, bn_b,
                                               bn_m, bn_v, ln_g, ln_b, out);
}